// round 1
// baseline (speedup 1.0000x reference)
#include <cuda_runtime.h>

#define EMBED  1024
#define NHEADS 16
#define DHEAD  64
#define BATCH  2
#define SEQ    2048
#define ROWS   (BATCH * SEQ)   // 4096

// Scratch for Q/K/V in [B][H][N][Dh] layout (16 MB each)
__device__ float g_q[BATCH * NHEADS * SEQ * DHEAD];
__device__ float g_k[BATCH * NHEADS * SEQ * DHEAD];
__device__ float g_v[BATCH * NHEADS * SEQ * DHEAD];

// ---------------------------------------------------------------------------
// Fused QKV projection: out = x @ W, split into heads on the fly.
// grid = (1024/128, 4096/128, 3), block = 256 threads, 128x128 tile, 8x8/thread
// ---------------------------------------------------------------------------
__global__ __launch_bounds__(256) void qkv_gemm_kernel(
    const float* __restrict__ x,
    const float* __restrict__ w0,
    const float* __restrict__ w1,
    const float* __restrict__ w2)
{
    const float* W   = (blockIdx.z == 0) ? w0 : (blockIdx.z == 1) ? w1 : w2;
    float*       dst = (blockIdx.z == 0) ? g_q : (blockIdx.z == 1) ? g_k : g_v;

    __shared__ float As[16][132];  // [kk][row-in-tile], padded
    __shared__ float Bs[16][132];  // [kk][col-in-tile], padded

    const int tid = threadIdx.x;
    const int tx  = tid & 15;      // 0..15 -> 8 output cols
    const int ty  = tid >> 4;      // 0..15 -> 8 output rows
    const int row0 = blockIdx.y * 128;
    const int col0 = blockIdx.x * 128;

    float acc[8][8];
    #pragma unroll
    for (int i = 0; i < 8; i++)
        #pragma unroll
        for (int j = 0; j < 8; j++) acc[i][j] = 0.f;

    for (int k0 = 0; k0 < EMBED; k0 += 16) {
        // A tile: x[row0..+128)[k0..+16), float4 along k, transpose into As
        #pragma unroll
        for (int i = tid; i < 512; i += 256) {
            int r  = i >> 2;
            int kc = (i & 3) * 4;
            float4 v = *(const float4*)&x[(row0 + r) * EMBED + k0 + kc];
            As[kc + 0][r] = v.x; As[kc + 1][r] = v.y;
            As[kc + 2][r] = v.z; As[kc + 3][r] = v.w;
        }
        // B tile: W[k0..+16)[col0..+128), float4 along cols
        #pragma unroll
        for (int i = tid; i < 512; i += 256) {
            int kk = i >> 5;
            int c  = (i & 31) * 4;
            *(float4*)&Bs[kk][c] = *(const float4*)&W[(k0 + kk) * EMBED + col0 + c];
        }
        __syncthreads();

        #pragma unroll
        for (int kk = 0; kk < 16; kk++) {
            float a[8], b[8];
            *(float4*)&a[0] = *(float4*)&As[kk][ty * 8];
            *(float4*)&a[4] = *(float4*)&As[kk][ty * 8 + 4];
            *(float4*)&b[0] = *(float4*)&Bs[kk][tx * 8];
            *(float4*)&b[4] = *(float4*)&Bs[kk][tx * 8 + 4];
            #pragma unroll
            for (int i = 0; i < 8; i++)
                #pragma unroll
                for (int j = 0; j < 8; j++)
                    acc[i][j] += a[i] * b[j];
        }
        __syncthreads();
    }

    // Write to [b][h][n][dh] scratch. 4-aligned col groups never straddle a head.
    #pragma unroll
    for (int i = 0; i < 8; i++) {
        int r = row0 + ty * 8 + i;
        int b = r >> 11;         // / SEQ
        int n = r & (SEQ - 1);
        #pragma unroll
        for (int j4 = 0; j4 < 8; j4 += 4) {
            int c  = col0 + tx * 8 + j4;
            int h  = c >> 6;
            int dh = c & 63;
            float4 v = make_float4(acc[i][j4], acc[i][j4 + 1], acc[i][j4 + 2], acc[i][j4 + 3]);
            *(float4*)&dst[(((b * NHEADS + h) * SEQ + n) * DHEAD) + dh] = v;
        }
    }
}

// ---------------------------------------------------------------------------
// Flash attention: one block per (q-tile of 64, head, batch). 256 threads:
// thread t handles row r=t/4, score/output cols cc = (t%4)*16 .. +16.
// Q row lives in 64 registers. K tile XOR-swizzled to kill 4-way conflicts.
// ---------------------------------------------------------------------------
#define PADROW 68                      // 64 + 4 floats
#define ATT_SMEM (3 * 64 * PADROW * 4) // Ks + Vs + Ps = 52224 B

__global__ __launch_bounds__(256) void attn_kernel(float* __restrict__ out)
{
    extern __shared__ float smem[];
    float* Ks = smem;
    float* Vs = smem + 64 * PADROW;
    float* Ps = smem + 2 * 64 * PADROW;

    const int tid = threadIdx.x;
    const int r   = tid >> 2;   // 0..63 query row in tile
    const int g   = tid & 3;    // col group
    const int b   = blockIdx.z;
    const int h   = blockIdx.y;
    const int q0  = blockIdx.x * 64;

    const float* Qg = g_q + (size_t)(b * NHEADS + h) * SEQ * DHEAD;
    const float* Kg = g_k + (size_t)(b * NHEADS + h) * SEQ * DHEAD;
    const float* Vg = g_v + (size_t)(b * NHEADS + h) * SEQ * DHEAD;

    // Stage Q tile through Ps, then pull own row into registers
    for (int i = tid; i < 64 * 16; i += 256) {
        int row = i >> 4, c4 = i & 15;
        *(float4*)&Ps[row * PADROW + c4 * 4] =
            *(const float4*)&Qg[(q0 + row) * DHEAD + c4 * 4];
    }
    __syncthreads();
    float qreg[64];
    #pragma unroll
    for (int d4 = 0; d4 < 16; d4++) {
        float4 v = *(float4*)&Ps[r * PADROW + d4 * 4];
        qreg[4 * d4 + 0] = v.x; qreg[4 * d4 + 1] = v.y;
        qreg[4 * d4 + 2] = v.z; qreg[4 * d4 + 3] = v.w;
    }
    __syncthreads();

    float m = -1e30f, l = 0.f;
    float o[16];
    #pragma unroll
    for (int j = 0; j < 16; j++) o[j] = 0.f;

    for (int kt = 0; kt < SEQ / 64; kt++) {
        const int k0 = kt * 64;
        // Load K (swizzled) + V (plain)
        for (int i = tid; i < 64 * 16; i += 256) {
            int row = i >> 4, c4 = i & 15;
            float4 kv = *(const float4*)&Kg[(k0 + row) * DHEAD + c4 * 4];
            *(float4*)&Ks[row * PADROW + (c4 ^ (row >> 4)) * 4] = kv;
            float4 vv = *(const float4*)&Vg[(k0 + row) * DHEAD + c4 * 4];
            *(float4*)&Vs[row * PADROW + c4 * 4] = vv;
        }
        __syncthreads();

        // S = Q @ K^T (scaled)
        float p[16];
        float mloc = -1e30f;
        #pragma unroll
        for (int j = 0; j < 16; j++) {
            const int cc = g * 16 + j;
            const int hi = cc >> 4;   // == g
            float acc = 0.f;
            #pragma unroll
            for (int d4 = 0; d4 < 16; d4++) {
                float4 kv = *(float4*)&Ks[cc * PADROW + (d4 ^ hi) * 4];
                acc += qreg[4 * d4 + 0] * kv.x + qreg[4 * d4 + 1] * kv.y
                     + qreg[4 * d4 + 2] * kv.z + qreg[4 * d4 + 3] * kv.w;
            }
            acc *= 0.125f;            // 1/sqrt(64)
            p[j] = acc;
            mloc = fmaxf(mloc, acc);
        }
        // Row reductions across the 4 lanes of this row
        mloc = fmaxf(mloc, __shfl_xor_sync(0xffffffffu, mloc, 1));
        mloc = fmaxf(mloc, __shfl_xor_sync(0xffffffffu, mloc, 2));
        float mnew = fmaxf(m, mloc);
        float corr = __expf(m - mnew);
        float lloc = 0.f;
        #pragma unroll
        for (int j = 0; j < 16; j++) { p[j] = __expf(p[j] - mnew); lloc += p[j]; }
        lloc += __shfl_xor_sync(0xffffffffu, lloc, 1);
        lloc += __shfl_xor_sync(0xffffffffu, lloc, 2);
        l = l * corr + lloc;
        m = mnew;
        #pragma unroll
        for (int j = 0; j < 16; j++) o[j] *= corr;

        // Stage P
        #pragma unroll
        for (int j4 = 0; j4 < 4; j4++)
            *(float4*)&Ps[r * PADROW + g * 16 + j4 * 4] =
                make_float4(p[j4 * 4], p[j4 * 4 + 1], p[j4 * 4 + 2], p[j4 * 4 + 3]);
        __syncthreads();

        // O += P @ V
        #pragma unroll 4
        for (int k = 0; k < 64; k++) {
            float pv = Ps[r * PADROW + k];
            #pragma unroll
            for (int j4 = 0; j4 < 4; j4++) {
                float4 vv = *(float4*)&Vs[k * PADROW + g * 16 + j4 * 4];
                o[j4 * 4 + 0] += pv * vv.x;
                o[j4 * 4 + 1] += pv * vv.y;
                o[j4 * 4 + 2] += pv * vv.z;
                o[j4 * 4 + 3] += pv * vv.w;
            }
        }
        __syncthreads();
    }

    const float inv = 1.f / l;
    float* op = out + (size_t)(b * SEQ + q0 + r) * EMBED + h * DHEAD + g * 16;
    #pragma unroll
    for (int j4 = 0; j4 < 4; j4++)
        *(float4*)&op[j4 * 4] = make_float4(o[j4 * 4] * inv, o[j4 * 4 + 1] * inv,
                                            o[j4 * 4 + 2] * inv, o[j4 * 4 + 3] * inv);
}

// ---------------------------------------------------------------------------
extern "C" void kernel_launch(void* const* d_in, const int* in_sizes, int n_in,
                              void* d_out, int out_size)
{
    const float* x  = (const float*)d_in[0];
    const float* wq = (const float*)d_in[1];
    const float* wk = (const float*)d_in[2];
    const float* wv = (const float*)d_in[3];
    float* out = (float*)d_out;

    cudaFuncSetAttribute(attn_kernel, cudaFuncAttributeMaxDynamicSharedMemorySize, ATT_SMEM);

    dim3 gg(EMBED / 128, ROWS / 128, 3);
    qkv_gemm_kernel<<<gg, 256>>>(x, wq, wk, wv);

    dim3 ga(SEQ / 64, NHEADS, BATCH);
    attn_kernel<<<ga, 256, ATT_SMEM>>>(out);
}